// round 6
// baseline (speedup 1.0000x reference)
#include <cuda_runtime.h>
#include <cuda_bf16.h>

// FeedForwardQuantum: out = relu(cos(x+theta) @ W1 + b1) @ W2 + b2
// B*S = 524288 tokens, E=8, F=32, all fp32.
//
// Strategy: fp32 packed-pair math via Blackwell fma.rn.f32x2 (FFMA2, 2x fp32
// fma throughput). GEMM2 fused into GEMM1's f-loop so h[32] is never stored.
// Weights in smem (broadcast LDS.64), amortized over TPT tokens/thread.

#define BLK 128
#define TPT 2

__device__ __forceinline__ unsigned long long pack2(float lo, float hi) {
    unsigned long long r;
    asm("mov.b64 %0, {%1, %2};" : "=l"(r) : "f"(lo), "f"(hi));
    return r;
}
__device__ __forceinline__ void unpack2(unsigned long long v, float& lo, float& hi) {
    asm("mov.b64 {%0, %1}, %2;" : "=f"(lo), "=f"(hi) : "l"(v));
}
__device__ __forceinline__ unsigned long long ffma2(unsigned long long a,
                                                    unsigned long long b,
                                                    unsigned long long c) {
    unsigned long long d;
    asm("fma.rn.f32x2 %0, %1, %2, %3;" : "=l"(d) : "l"(a), "l"(b), "l"(c));
    return d;
}

__global__ __launch_bounds__(BLK, 4)
void ffq_kernel(const float* __restrict__ x,
                const float* __restrict__ theta,
                const float* __restrict__ w1,   // [8, 32] row-major
                const float* __restrict__ b1,   // [32]
                const float* __restrict__ w2,   // [32, 8] row-major
                const float* __restrict__ b2,   // [8]
                float* __restrict__ out,
                int n_tok)
{
    // Packed-pair shared weights.
    // s_w1[e][j] = (w1[e][2j], w1[e][2j+1])       pairs over F
    // s_w2[f][i] = (w2[f][2i], w2[f][2i+1])       pairs over E
    __shared__ unsigned long long s_w1[8][16];
    __shared__ unsigned long long s_b1[16];
    __shared__ unsigned long long s_w2[32][4];
    __shared__ unsigned long long s_b2[4];
    __shared__ float s_th[8];

    const int tid = threadIdx.x;

    // Cooperative smem fill. w1/w2 pairs are contiguous in global memory,
    // so a straight float2 copy produces the packed layout.
    if (tid < 128) {
        reinterpret_cast<float2*>(s_w1)[tid] = reinterpret_cast<const float2*>(w1)[tid];
        reinterpret_cast<float2*>(s_w2)[tid] = reinterpret_cast<const float2*>(w2)[tid];
    }
    if (tid < 16) reinterpret_cast<float2*>(s_b1)[tid] = reinterpret_cast<const float2*>(b1)[tid];
    if (tid < 4)  reinterpret_cast<float2*>(s_b2)[tid] = reinterpret_cast<const float2*>(b2)[tid];
    if (tid < 8)  s_th[tid] = theta[tid];
    __syncthreads();

    float th[8];
#pragma unroll
    for (int e = 0; e < 8; e++) th[e] = s_th[e];

    const long base = (long)blockIdx.x * (BLK * TPT) + tid;

    long tk[TPT];
    bool valid[TPT];
    unsigned long long qb[TPT][8];   // broadcast pairs (q_e, q_e)

#pragma unroll
    for (int k = 0; k < TPT; k++) {
        tk[k] = base + (long)k * BLK;
        valid[k] = (tk[k] < (long)n_tok);
        const long off = valid[k] ? tk[k] * 8 : 0;
        const float4 a0 = reinterpret_cast<const float4*>(x + off)[0];
        const float4 a1 = reinterpret_cast<const float4*>(x + off)[1];
        float q[8];
        q[0] = __cosf(a0.x + th[0]);
        q[1] = __cosf(a0.y + th[1]);
        q[2] = __cosf(a0.z + th[2]);
        q[3] = __cosf(a0.w + th[3]);
        q[4] = __cosf(a1.x + th[4]);
        q[5] = __cosf(a1.y + th[5]);
        q[6] = __cosf(a1.z + th[6]);
        q[7] = __cosf(a1.w + th[7]);
#pragma unroll
        for (int e = 0; e < 8; e++) qb[k][e] = pack2(q[e], q[e]);
    }

    // Output accumulators (4 E-pairs per token), seeded with b2.
    unsigned long long acc[TPT][4];
#pragma unroll
    for (int k = 0; k < TPT; k++)
#pragma unroll
        for (int i = 0; i < 4; i++) acc[k][i] = s_b2[i];

    // Fused GEMM1+ReLU+GEMM2 over F-pairs j = (2j, 2j+1).
#pragma unroll
    for (int j = 0; j < 16; j++) {
        unsigned long long w1p[8];
#pragma unroll
        for (int e = 0; e < 8; e++) w1p[e] = s_w1[e][j];
        const unsigned long long b1p = s_b1[j];
        unsigned long long wA[4], wB[4];
#pragma unroll
        for (int i = 0; i < 4; i++) {
            wA[i] = s_w2[2 * j + 0][i];
            wB[i] = s_w2[2 * j + 1][i];
        }
#pragma unroll
        for (int k = 0; k < TPT; k++) {
            unsigned long long h = b1p;
#pragma unroll
            for (int e = 0; e < 8; e++) h = ffma2(qb[k][e], w1p[e], h);
            float r0, r1;
            unpack2(h, r0, r1);
            r0 = fmaxf(r0, 0.0f);
            r1 = fmaxf(r1, 0.0f);
            const unsigned long long rb0 = pack2(r0, r0);
            const unsigned long long rb1 = pack2(r1, r1);
#pragma unroll
            for (int i = 0; i < 4; i++) {
                acc[k][i] = ffma2(rb0, wA[i], acc[k][i]);
                acc[k][i] = ffma2(rb1, wB[i], acc[k][i]);
            }
        }
    }

#pragma unroll
    for (int k = 0; k < TPT; k++) {
        if (valid[k]) {
            float o[8];
#pragma unroll
            for (int i = 0; i < 4; i++) unpack2(acc[k][i], o[2 * i], o[2 * i + 1]);
            float4* dst = reinterpret_cast<float4*>(out + tk[k] * 8);
            dst[0] = make_float4(o[0], o[1], o[2], o[3]);
            dst[1] = make_float4(o[4], o[5], o[6], o[7]);
        }
    }
}

extern "C" void kernel_launch(void* const* d_in, const int* in_sizes, int n_in,
                              void* d_out, int out_size) {
    const float* x     = (const float*)d_in[0];
    const float* theta = (const float*)d_in[1];
    const float* w1    = (const float*)d_in[2];
    const float* b1    = (const float*)d_in[3];
    const float* w2    = (const float*)d_in[4];
    const float* b2    = (const float*)d_in[5];
    float* out = (float*)d_out;

    const int n_tok = in_sizes[0] / 8;                 // B*S tokens
    const int tok_per_blk = BLK * TPT;
    const int blocks = (n_tok + tok_per_blk - 1) / tok_per_blk;

    ffq_kernel<<<blocks, BLK>>>(x, theta, w1, b1, w2, b2, out, n_tok);
}